// round 11
// baseline (speedup 1.0000x reference)
#include <cuda_runtime.h>
#include <cuda_bf16.h>
#include <math.h>
#include <cstdint>

// ---------------- problem constants ----------------
constexpr int NB = 128;      // batch
constexpr int NT_STEPS = 46; // time steps
constexpr int NV = 8150;     // vocab
constexpr int NE = 300;      // embed dim
constexpr int NH = 128;      // lstm hidden
constexpr int NM = NB * NT_STEPS;  // 5888 rows
constexpr int G4H = 512;     // 4*H
constexpr int KV_PAD = 8192; // vocab K padded
constexpr int NBP = 320;     // embed out cols padded
constexpr int KE_PAD = 320;  // GEMM2 K

// ---------------- device scratch ----------------
__device__ __nv_bfloat16 g_ehi[2 * NM * NBP];
__device__ __nv_bfloat16 g_elo[2 * NM * NBP];
__device__ float g_xz[2 * NM * G4H];
__device__ float g_o [2 * NB * NT_STEPS * NH];
__device__ float g_a [NB * 1024];
__device__ __nv_bfloat16 g_eThi[2 * NBP * KV_PAD];
__device__ __nv_bfloat16 g_eTlo[2 * NBP * KV_PAD];
__device__ __nv_bfloat16 g_wThi[2 * G4H * KE_PAD];
__device__ __nv_bfloat16 g_wTlo[2 * G4H * KE_PAD];

__device__ __forceinline__ float sigmoidf(float x) { return 1.f / (1.f + expf(-x)); }

// ================= helpers =================
__device__ __forceinline__ void cpasync16(uint32_t dst, const void* src) {
    asm volatile("cp.async.cg.shared.global [%0], [%1], 16;" :: "r"(dst), "l"(src));
}
__device__ __forceinline__ uint32_t smem_u32(const void* p) {
    uint32_t a;
    asm("{ .reg .u64 t; cvta.to.shared.u64 t, %1; cvt.u32.u64 %0, t; }" : "=r"(a) : "l"(p));
    return a;
}
#define CP_COMMIT() asm volatile("cp.async.commit_group;" ::: "memory")
#define CP_WAIT0()  asm volatile("cp.async.wait_group 0;" ::: "memory")
#define CP_WAIT1()  asm volatile("cp.async.wait_group 1;" ::: "memory")
#define CP_WAIT2()  asm volatile("cp.async.wait_group 2;" ::: "memory")

__device__ __forceinline__ uint32_t pack_bf16(float a, float b) {
    __nv_bfloat16 ha = __float2bfloat16(a), hb = __float2bfloat16(b);
    return (uint32_t)__bfloat16_as_ushort(ha) | ((uint32_t)__bfloat16_as_ushort(hb) << 16);
}

__device__ __forceinline__ void mma16816(float* c, const uint32_t* a, uint32_t b0, uint32_t b1) {
    asm volatile(
        "mma.sync.aligned.m16n8k16.row.col.f32.bf16.bf16.f32 "
        "{%0,%1,%2,%3},{%4,%5,%6,%7},{%8,%9},{%0,%1,%2,%3};"
        : "+f"(c[0]), "+f"(c[1]), "+f"(c[2]), "+f"(c[3])
        : "r"(a[0]), "r"(a[1]), "r"(a[2]), "r"(a[3]), "r"(b0), "r"(b1));
}

// smem tile geometry: K-chunk 32 elems, row stride 40 elems (80B: 16B-aligned,
// 20-bank shift per row -> conflict-free fragment loads)
constexpr int KST = 40;

// Pass-major 3-pass split MMA over one staged 32-K chunk.
// Each pass sweeps ALL (i,j) accumulators before revisiting any one, so the
// dependent-MMA reuse distance is MFRAG*NFRAG instead of 1.
template<int MFRAG, int NFRAG>
__device__ __forceinline__ void compute_chunk(
    const char* AH, const char* AL, const char* BH, const char* BL,
    int wm, int wn, int qrow, int qcol, float (*c)[NFRAG][4])
{
#pragma unroll
    for (int kk = 0; kk < 32; kk += 16) {
        uint32_t ah[MFRAG][4], al[MFRAG][4];
#pragma unroll
        for (int i = 0; i < MFRAG; i++) {
            int r = wm + i * 16 + qrow;
            const char* pH = AH + (size_t)(r * KST + kk + qcol) * 2;
            const char* pL = AL + (size_t)(r * KST + kk + qcol) * 2;
            ah[i][0] = *(const uint32_t*)pH;
            ah[i][1] = *(const uint32_t*)(pH + 8 * KST * 2);
            ah[i][2] = *(const uint32_t*)(pH + 16);
            ah[i][3] = *(const uint32_t*)(pH + 8 * KST * 2 + 16);
            al[i][0] = *(const uint32_t*)pL;
            al[i][1] = *(const uint32_t*)(pL + 8 * KST * 2);
            al[i][2] = *(const uint32_t*)(pL + 16);
            al[i][3] = *(const uint32_t*)(pL + 8 * KST * 2 + 16);
        }
        // pass 1: Ahi * Bhi
#pragma unroll
        for (int j = 0; j < NFRAG; j++) {
            int n = wn + j * 8 + qrow;
            const char* qH = BH + (size_t)(n * KST + kk + qcol) * 2;
            uint32_t b0 = *(const uint32_t*)qH, b1 = *(const uint32_t*)(qH + 16);
#pragma unroll
            for (int i = 0; i < MFRAG; i++) mma16816(c[i][j], ah[i], b0, b1);
        }
        // pass 2: Ahi * Blo
#pragma unroll
        for (int j = 0; j < NFRAG; j++) {
            int n = wn + j * 8 + qrow;
            const char* qL = BL + (size_t)(n * KST + kk + qcol) * 2;
            uint32_t b0 = *(const uint32_t*)qL, b1 = *(const uint32_t*)(qL + 16);
#pragma unroll
            for (int i = 0; i < MFRAG; i++) mma16816(c[i][j], ah[i], b0, b1);
        }
        // pass 3: Alo * Bhi
#pragma unroll
        for (int j = 0; j < NFRAG; j++) {
            int n = wn + j * 8 + qrow;
            const char* qH = BH + (size_t)(n * KST + kk + qcol) * 2;
            uint32_t b0 = *(const uint32_t*)qH, b1 = *(const uint32_t*)(qH + 16);
#pragma unroll
            for (int i = 0; i < MFRAG; i++) mma16816(c[i][j], al[i], b0, b1);
        }
    }
}

// =====================================================================
// Transpose + bf16 hi/lo split:  D[n][k] = split(src[k][n]) zero-padded.
// =====================================================================
__global__ void convT_kernel(const float* __restrict__ S0, const float* __restrict__ S1,
                             int Rvalid, int Cvalid, int ld, int KPAD, int NTOT,
                             __nv_bfloat16* __restrict__ Dhi, __nv_bfloat16* __restrict__ Dlo,
                             size_t dstride)
{
    int s = blockIdx.z;
    const float* S = s ? S1 : S0;
    __nv_bfloat16* dh = Dhi + (size_t)s * dstride;
    __nv_bfloat16* dl = Dlo + (size_t)s * dstride;
    __shared__ float tile[32][33];
    int tx = threadIdx.x, ty = threadIdx.y;
    int gk = blockIdx.x * 32 + ty;
    int gn = blockIdx.y * 32 + tx;
    tile[ty][tx] = (gk < Rvalid && gn < Cvalid) ? S[(size_t)gk * ld + gn] : 0.f;
    __syncthreads();
    int k2 = blockIdx.x * 32 + tx;
    int n2 = blockIdx.y * 32 + ty;
    if (n2 < NTOT) {
        float v = tile[tx][ty];
        __nv_bfloat16 h = __float2bfloat16(v);
        __nv_bfloat16 l = __float2bfloat16(v - __bfloat162float(h));
        dh[(size_t)n2 * KPAD + k2] = h;
        dl[(size_t)n2 * KPAD + k2] = l;
    }
}

// =====================================================================
// GEMM1: e = X @ embed. Block 128x80, 256 thr, 8 warps (32x40, 4m x 2n).
// K-chunk 32, 3-stage cp.async pipeline, ONE barrier per chunk.
// storeA writes 2 chunks ahead (buffer last read 2 barriers ago).
// Grid (4 n, 46 m, 2 s) = 368 CTAs, 2/SM resident.
// =====================================================================
constexpr int G1_A = 128 * KST * 2;   // 10240 per operand per stage
constexpr int G1_B = 80 * KST * 2;    // 6400
constexpr int G1_STAGE = 2 * G1_A + 2 * G1_B;  // 33280
constexpr int G1_SMEM = 3 * G1_STAGE;          // 99840

__global__ void __launch_bounds__(256, 2) gemm1_kernel(
    const float* __restrict__ X0, const float* __restrict__ X1,
    const __nv_bfloat16* __restrict__ BTh, const __nv_bfloat16* __restrict__ BTl,
    __nv_bfloat16* __restrict__ Eh, __nv_bfloat16* __restrict__ El)
{
    extern __shared__ char sm[];
    const int s = blockIdx.z;
    const float* A = s ? X1 : X0;
    const __nv_bfloat16* bth = BTh + (size_t)s * NBP * KV_PAD;
    const __nv_bfloat16* btl = BTl + (size_t)s * NBP * KV_PAD;
    __nv_bfloat16* eh = Eh + (size_t)s * NM * NBP;
    __nv_bfloat16* el = El + (size_t)s * NM * NBP;
    const int m0 = blockIdx.y * 128;
    const int n0 = blockIdx.x * 80;

    const uint32_t sb = smem_u32(sm);
    const int tid = threadIdx.x;
    const int lane = tid & 31, warp = tid >> 5;
    const int wm = (warp >> 1) * 32, wn = (warp & 1) * 40;
    const int qrow = lane >> 2, qcol = (lane & 3) * 2;
    const int arow = tid >> 1, akb = (tid & 1) * 16;

    auto stageB = [&](int it, int buf) {
        const int k0 = it * 32;
        uint32_t base = sb + buf * G1_STAGE + 2 * G1_A;
        for (int x = tid; x < 640; x += 256) {
            int row = x >> 3, rem = x & 7;
            int half = rem >> 2, seg = rem & 3;
            const __nv_bfloat16* src = (half ? btl : bth)
                + (size_t)(n0 + row) * KV_PAD + k0 + seg * 8;
            uint32_t so = base + half * G1_B + (uint32_t)(row * 80 + seg * 16);
            cpasync16(so, src);
        }
    };
    auto loadA = [&](int it, float* v) {
        const int k0 = it * 32;
        const float* p = A + (size_t)(m0 + arow) * NV + k0 + akb;
        if (k0 + 32 <= NV) {
#pragma unroll
            for (int j = 0; j < 8; j++) { float2 t = ((const float2*)p)[j]; v[2*j] = t.x; v[2*j+1] = t.y; }
        } else {
#pragma unroll
            for (int j = 0; j < 16; j++) { int gk = k0 + akb + j; v[j] = (gk < NV) ? p[j] : 0.f; }
        }
    };
    auto storeA = [&](int buf, const float* v) {
        uint32_t hi[8], lo[8];
#pragma unroll
        for (int j = 0; j < 8; j++) {
            float v0 = v[2*j], v1 = v[2*j+1];
            float h0 = __bfloat162float(__float2bfloat16(v0));
            float h1 = __bfloat162float(__float2bfloat16(v1));
            hi[j] = pack_bf16(v0, v1);
            lo[j] = pack_bf16(v0 - h0, v1 - h1);
        }
        char* dH = sm + buf * G1_STAGE + arow * 80 + akb * 2;
        char* dL = dH + G1_A;
        *(uint4*)(dH)      = *(uint4*)(hi);
        *(uint4*)(dH + 16) = *(uint4*)(hi + 4);
        *(uint4*)(dL)      = *(uint4*)(lo);
        *(uint4*)(dL + 16) = *(uint4*)(lo + 4);
    };

    // ---- prologue: fill stages 0 and 1 ----
    stageB(0, 0); CP_COMMIT();
    stageB(1, 1); CP_COMMIT();
    {
        float v[16];
        loadA(0, v); storeA(0, v);
        loadA(1, v); storeA(1, v);
    }
    CP_WAIT1();           // stage 0 B complete
    __syncthreads();

    float c[2][5][4];
#pragma unroll
    for (int i = 0; i < 2; i++)
#pragma unroll
        for (int j = 0; j < 5; j++)
#pragma unroll
            for (int r = 0; r < 4; r++) c[i][j][r] = 0.f;

    const int iters = KV_PAD / 32;  // 256
    float vp[16];
    for (int it = 0; it < iters; ++it) {
        const int cur = it % 3;
        const bool pf = (it + 2 < iters);
        if (pf) {
            stageB(it + 2, (it + 2) % 3); CP_COMMIT();   // buffer last read at it-1
            loadA(it + 2, vp);
        }
        if (pf) { CP_WAIT2(); } else { CP_WAIT0(); }     // chunk it's B complete
        const char* base = sm + cur * G1_STAGE;
        compute_chunk<2, 5>(base, base + G1_A, base + 2 * G1_A, base + 2 * G1_A + G1_B,
                            wm, wn, qrow, qcol, c);
        if (pf) storeA((it + 2) % 3, vp);                // LDG latency hidden by compute
        __syncthreads();                                 // single barrier per chunk
    }

    // epilogue: write e hi/lo
#pragma unroll
    for (int i = 0; i < 2; i++) {
        int r0 = m0 + wm + i * 16 + qrow;
#pragma unroll
        for (int j = 0; j < 5; j++) {
            int col = n0 + wn + j * 8 + qcol;
            float v0 = c[i][j][0], v1 = c[i][j][1];
            float h0 = __bfloat162float(__float2bfloat16(v0));
            float h1 = __bfloat162float(__float2bfloat16(v1));
            *(uint32_t*)&eh[(size_t)r0 * NBP + col] = pack_bf16(v0, v1);
            *(uint32_t*)&el[(size_t)r0 * NBP + col] = pack_bf16(v0 - h0, v1 - h1);
            float v2 = c[i][j][2], v3 = c[i][j][3];
            float h2 = __bfloat162float(__float2bfloat16(v2));
            float h3 = __bfloat162float(__float2bfloat16(v3));
            *(uint32_t*)&eh[(size_t)(r0 + 8) * NBP + col] = pack_bf16(v2, v3);
            *(uint32_t*)&el[(size_t)(r0 + 8) * NBP + col] = pack_bf16(v2 - h2, v3 - h3);
        }
    }
}

// =====================================================================
// GEMM2: xz = e @ W[:300]. Block 128x128, 256 thr, warp 64x32 (2m x 4n).
// K-chunk 32, 3-stage (R6 machinery + pass-major compute).
// =====================================================================
constexpr int G2_BUF = 128 * KST * 2;    // 10240
constexpr int G2_SMEM = 3 * 4 * G2_BUF;  // 122880

__global__ void __launch_bounds__(256, 1) gemm2_kernel(
    const __nv_bfloat16* __restrict__ Eh, const __nv_bfloat16* __restrict__ El,
    const __nv_bfloat16* __restrict__ Wh, const __nv_bfloat16* __restrict__ Wl,
    float* __restrict__ XZ)
{
    extern __shared__ char sm[];
    const int s = blockIdx.z;
    const __nv_bfloat16* ah = Eh + (size_t)s * NM * NBP;
    const __nv_bfloat16* al = El + (size_t)s * NM * NBP;
    const __nv_bfloat16* bh = Wh + (size_t)s * G4H * KE_PAD;
    const __nv_bfloat16* bl = Wl + (size_t)s * G4H * KE_PAD;
    float* xz = XZ + (size_t)s * NM * G4H;
    const int m0 = blockIdx.x * 128;
    const int n0 = blockIdx.y * 128;

    const uint32_t sb = smem_u32(sm);
    char* AHb = sm;
    char* ALb = sm + 3 * G2_BUF;
    char* BHb = sm + 6 * G2_BUF;
    char* BLb = sm + 9 * G2_BUF;

    const int tid = threadIdx.x;
    const int lane = tid & 31, warp = tid >> 5;
    const int wm = (warp >> 2) * 64, wn = (warp & 3) * 32;
    const int qrow = lane >> 2, qcol = (lane & 3) * 2;

    auto stage = [&](int it, int buf) {
        const int k0 = it * 32;
        uint32_t dAH = sb + (uint32_t)(AHb - sm) + buf * G2_BUF;
        uint32_t dAL = sb + (uint32_t)(ALb - sm) + buf * G2_BUF;
        uint32_t dBH = sb + (uint32_t)(BHb - sm) + buf * G2_BUF;
        uint32_t dBL = sb + (uint32_t)(BLb - sm) + buf * G2_BUF;
#pragma unroll
        for (int x = tid; x < 512; x += 256) {
            int row = x >> 2, seg = x & 3;
            uint32_t so = (uint32_t)(row * KST + seg * 8) * 2;
            size_t ga = (size_t)(m0 + row) * NBP + k0 + seg * 8;
            size_t gb = (size_t)(n0 + row) * KE_PAD + k0 + seg * 8;
            cpasync16(dAH + so, ah + ga);
            cpasync16(dAL + so, al + ga);
            cpasync16(dBH + so, bh + gb);
            cpasync16(dBL + so, bl + gb);
        }
    };

    stage(0, 0); CP_COMMIT();
    stage(1, 1); CP_COMMIT();
    CP_WAIT0();
    __syncthreads();

    float c[4][4][4];
#pragma unroll
    for (int i = 0; i < 4; i++)
#pragma unroll
        for (int j = 0; j < 4; j++)
#pragma unroll
            for (int r = 0; r < 4; r++) c[i][j][r] = 0.f;

    const int iters = KE_PAD / 32;  // 10
    for (int it = 0; it < iters; ++it) {
        const int cur = it % 3;
        const bool pf = (it + 2 < iters);
        if (pf) { stage(it + 2, (it + 2) % 3); CP_COMMIT(); }
        if (pf) { CP_WAIT1(); } else { CP_WAIT0(); }
        compute_chunk<4, 4>(AHb + cur * G2_BUF, ALb + cur * G2_BUF,
                            BHb + cur * G2_BUF, BLb + cur * G2_BUF,
                            wm, wn, qrow, qcol, c);
        __syncthreads();
    }

#pragma unroll
    for (int i = 0; i < 4; i++) {
        int r0 = m0 + wm + i * 16 + qrow;
#pragma unroll
        for (int j = 0; j < 4; j++) {
            int col = n0 + wn + j * 8 + qcol;
            *(float2*)&xz[(size_t)r0 * G4H + col]       = make_float2(c[i][j][0], c[i][j][1]);
            *(float2*)&xz[(size_t)(r0 + 8) * G4H + col] = make_float2(c[i][j][2], c[i][j][3]);
        }
    }
}

// =====================================================================
// LSTM recurrence (R6 version: scalar coalesced Wr reads).
// =====================================================================
__global__ void __launch_bounds__(512) lstm_kernel(
    const float* __restrict__ Wl1, const float* __restrict__ Wl2,
    const float* __restrict__ lng1, const float* __restrict__ lnb1,
    const float* __restrict__ lng2, const float* __restrict__ lnb2)
{
    int s = blockIdx.y;
    const float* Wr  = (s ? Wl2 : Wl1) + NE * G4H;
    const float* lng = s ? lng2 : lng1;
    const float* lnb = s ? lnb2 : lnb1;
    const float* xz  = g_xz + (size_t)s * NM * G4H;

    int b0   = blockIdx.x * 4;
    int col  = threadIdx.x;
    int w    = threadIdx.x >> 5;
    int lane = threadIdx.x & 31;
    int rrl  = threadIdx.x >> 7;
    int idx  = threadIdx.x & 127;

    __shared__ float h_sh[4][128];
    __shared__ float zbuf[4][512];
    __shared__ float mu_s[4][4], rstd_s[4][4];
    __shared__ float wp1[16], wp2[16];

    h_sh[rrl][idx] = 0.f;
    float c_val = 0.f;

    float gi = lng[idx],       gj = lng[128 + idx], gf = lng[256 + idx];
    float go = lng[384 + idx], gc = lng[512 + idx];
    float bi = lnb[idx],       bj = lnb[128 + idx], bf = lnb[256 + idx];
    float bo = lnb[384 + idx], bc = lnb[512 + idx];
    __syncthreads();

    for (int t = 0; t < NT_STEPS; t++) {
        float a0 = xz[(size_t)((b0 + 0) * NT_STEPS + t) * G4H + col];
        float a1 = xz[(size_t)((b0 + 1) * NT_STEPS + t) * G4H + col];
        float a2 = xz[(size_t)((b0 + 2) * NT_STEPS + t) * G4H + col];
        float a3 = xz[(size_t)((b0 + 3) * NT_STEPS + t) * G4H + col];

#pragma unroll 8
        for (int k = 0; k < NH; k += 4) {
            float4 h0 = *(const float4*)&h_sh[0][k];
            float4 h1 = *(const float4*)&h_sh[1][k];
            float4 h2 = *(const float4*)&h_sh[2][k];
            float4 h3 = *(const float4*)&h_sh[3][k];
            float w0 = Wr[(k + 0) * G4H + col];
            float w1 = Wr[(k + 1) * G4H + col];
            float w2 = Wr[(k + 2) * G4H + col];
            float w3 = Wr[(k + 3) * G4H + col];
            a0 = fmaf(h0.x, w0, fmaf(h0.y, w1, fmaf(h0.z, w2, fmaf(h0.w, w3, a0))));
            a1 = fmaf(h1.x, w0, fmaf(h1.y, w1, fmaf(h1.z, w2, fmaf(h1.w, w3, a1))));
            a2 = fmaf(h2.x, w0, fmaf(h2.y, w1, fmaf(h2.z, w2, fmaf(h2.w, w3, a2))));
            a3 = fmaf(h3.x, w0, fmaf(h3.y, w1, fmaf(h3.z, w2, fmaf(h3.w, w3, a3))));
        }
        zbuf[0][col] = a0; zbuf[1][col] = a1; zbuf[2][col] = a2; zbuf[3][col] = a3;
        __syncthreads();

        {
            int rr = w >> 2, gg = w & 3;
            float s1 = 0.f, s2 = 0.f;
#pragma unroll
            for (int i = 0; i < 4; i++) {
                float v = zbuf[rr][gg * 128 + lane + 32 * i];
                s1 += v;
                s2 = fmaf(v, v, s2);
            }
#pragma unroll
            for (int off = 16; off; off >>= 1) {
                s1 += __shfl_xor_sync(0xffffffffu, s1, off);
                s2 += __shfl_xor_sync(0xffffffffu, s2, off);
            }
            if (lane == 0) {
                float mu  = s1 * (1.f / 128.f);
                float var = fmaxf(s2 * (1.f / 128.f) - mu * mu, 0.f);
                mu_s[rr][gg]   = mu;
                rstd_s[rr][gg] = rsqrtf(var + 1e-12f);
            }
        }
        __syncthreads();

        int r = rrl;
        float zi = (zbuf[r][idx]       - mu_s[r][0]) * rstd_s[r][0] * gi + bi;
        float zj = (zbuf[r][128 + idx] - mu_s[r][1]) * rstd_s[r][1] * gj + bj;
        float zf = (zbuf[r][256 + idx] - mu_s[r][2]) * rstd_s[r][2] * gf + bf;
        float zo = (zbuf[r][384 + idx] - mu_s[r][3]) * rstd_s[r][3] * go + bo;
        float cn = c_val * sigmoidf(zf + 1.f) + sigmoidf(zi) * fmaxf(zj, 0.f);
        c_val = cn;

        float s1 = cn, s2 = cn * cn;
#pragma unroll
        for (int off = 16; off; off >>= 1) {
            s1 += __shfl_xor_sync(0xffffffffu, s1, off);
            s2 += __shfl_xor_sync(0xffffffffu, s2, off);
        }
        if (lane == 0) { wp1[w] = s1; wp2[w] = s2; }
        __syncthreads();
        float ss1 = wp1[4 * r] + wp1[4 * r + 1] + wp1[4 * r + 2] + wp1[4 * r + 3];
        float ss2 = wp2[4 * r] + wp2[4 * r + 1] + wp2[4 * r + 2] + wp2[4 * r + 3];
        float mu_c   = ss1 * (1.f / 128.f);
        float var_c  = fmaxf(ss2 * (1.f / 128.f) - mu_c * mu_c, 0.f);
        float rstd_c = rsqrtf(var_c + 1e-12f);

        float hn = fmaxf((cn - mu_c) * rstd_c * gc + bc, 0.f) * sigmoidf(zo);
        h_sh[r][idx] = hn;
        g_o[(((size_t)s * NB + b0 + r) * NT_STEPS + t) * NH + idx] = hn;
        __syncthreads();
    }
}

// =====================================================================
// Attention + fc1.
// =====================================================================
__global__ void __launch_bounds__(512) attn_fc1_kernel(
    const float* __restrict__ v1, const float* __restrict__ Wo1, const float* __restrict__ bo1,
    const float* __restrict__ v2, const float* __restrict__ Wo2, const float* __restrict__ bo2)
{
    int s = blockIdx.y, b = blockIdx.x;
    const float* vv = s ? v2  : v1;
    const float* Wo = s ? Wo2 : Wo1;
    const float* bo = s ? bo2 : bo1;
    const float* ob = g_o + ((size_t)(s * NB + b) * NT_STEPS) * NH;

    __shared__ float sc[64];
    __shared__ float ctx[128];
    int w = threadIdx.x >> 5, lane = threadIdx.x & 31;

    for (int t = w; t < NT_STEPS; t += 16) {
        float p = 0.f;
#pragma unroll
        for (int i = 0; i < 4; i++)
            p = fmaf(ob[t * NH + lane + 32 * i], vv[lane + 32 * i], p);
#pragma unroll
        for (int off = 16; off; off >>= 1) p += __shfl_xor_sync(0xffffffffu, p, off);
        if (lane == 0) sc[t] = p;
    }
    __syncthreads();

    if (w == 0) {
        float v0 = sc[lane];
        float vb = (lane + 32 < NT_STEPS) ? sc[lane + 32] : -1e30f;
        float mx = fmaxf(v0, vb);
#pragma unroll
        for (int off = 16; off; off >>= 1) mx = fmaxf(mx, __shfl_xor_sync(0xffffffffu, mx, off));
        float e0 = expf(v0 - mx);
        float e1 = (lane + 32 < NT_STEPS) ? expf(vb - mx) : 0.f;
        float sm = e0 + e1;
#pragma unroll
        for (int off = 16; off; off >>= 1) sm += __shfl_xor_sync(0xffffffffu, sm, off);
        float inv = 1.f / sm;
        sc[lane] = e0 * inv;
        if (lane + 32 < NT_STEPS) sc[lane + 32] = e1 * inv;
    }
    __syncthreads();

    if (threadIdx.x < NH) {
        float p = 0.f;
        for (int t = 0; t < NT_STEPS; t++) p = fmaf(sc[t], ob[t * NH + threadIdx.x], p);
        ctx[threadIdx.x] = p;
    }
    __syncthreads();

    int j = threadIdx.x;
    float accv = bo[j];
#pragma unroll 4
    for (int h = 0; h < NH; h++) accv = fmaf(ctx[h], Wo[h * 512 + j], accv);
    g_a[(size_t)b * 1024 + s * 512 + j] = fmaxf(accv, 0.f);
}

// =====================================================================
// fc2 + fc3.
// =====================================================================
__global__ void __launch_bounds__(512) fc23_kernel(
    const float* __restrict__ Wh, const float* __restrict__ bh,
    const float* __restrict__ Wout, const float* __restrict__ bout,
    float* __restrict__ out)
{
    int b0 = blockIdx.x * 4;
    __shared__ float a_sh[4][1024];
    __shared__ float hid[4][512];
    int tid = threadIdx.x;

#pragma unroll
    for (int p = 0; p < 8; p++) {
        int i = p * 512 + tid;
        a_sh[i >> 10][i & 1023] = g_a[(size_t)b0 * 1024 + i];
    }
    __syncthreads();

    float acc0 = bh[tid], acc1 = bh[tid], acc2 = bh[tid], acc3 = bh[tid];
    for (int k = 0; k < 1024; k++) {
        float wv = Wh[k * 512 + tid];
        acc0 = fmaf(a_sh[0][k], wv, acc0);
        acc1 = fmaf(a_sh[1][k], wv, acc1);
        acc2 = fmaf(a_sh[2][k], wv, acc2);
        acc3 = fmaf(a_sh[3][k], wv, acc3);
    }
    hid[0][tid] = fmaxf(acc0, 0.f);
    hid[1][tid] = fmaxf(acc1, 0.f);
    hid[2][tid] = fmaxf(acc2, 0.f);
    hid[3][tid] = fmaxf(acc3, 0.f);
    __syncthreads();

    int w = tid >> 5, lane = tid & 31;
    if (w < 8) {
        int r = w >> 1, oc = w & 1;
        float p = 0.f;
#pragma unroll
        for (int i = 0; i < 16; i++) {
            int k = lane + 32 * i;
            p = fmaf(hid[r][k], Wout[k * 2 + oc], p);
        }
#pragma unroll
        for (int off = 16; off; off >>= 1) p += __shfl_xor_sync(0xffffffffu, p, off);
        if (lane == 0) out[(b0 + r) * 2 + oc] = p + bout[oc];
    }
}

// =====================================================================
extern "C" void kernel_launch(void* const* d_in, const int* in_sizes, int n_in,
                              void* d_out, int out_size)
{
    const float* x1   = (const float*)d_in[0];
    const float* x2   = (const float*)d_in[1];
    const float* em1  = (const float*)d_in[2];
    const float* em2  = (const float*)d_in[3];
    const float* Wl1  = (const float*)d_in[4];
    const float* Wl2  = (const float*)d_in[5];
    const float* lng1 = (const float*)d_in[6];
    const float* lnb1 = (const float*)d_in[7];
    const float* lng2 = (const float*)d_in[8];
    const float* lnb2 = (const float*)d_in[9];
    const float* v1   = (const float*)d_in[10];
    const float* Wo1  = (const float*)d_in[11];
    const float* bo1  = (const float*)d_in[12];
    const float* v2   = (const float*)d_in[13];
    const float* Wo2  = (const float*)d_in[14];
    const float* bo2  = (const float*)d_in[15];
    const float* Wh   = (const float*)d_in[16];
    const float* bh   = (const float*)d_in[17];
    const float* Wout = (const float*)d_in[18];
    const float* bout = (const float*)d_in[19];
    float* out = (float*)d_out;

    float *pxz;
    __nv_bfloat16 *pehi, *pelo, *peThi, *peTlo, *pwThi, *pwTlo;
    cudaGetSymbolAddress((void**)&pxz,   g_xz);
    cudaGetSymbolAddress((void**)&pehi,  g_ehi);
    cudaGetSymbolAddress((void**)&pelo,  g_elo);
    cudaGetSymbolAddress((void**)&peThi, g_eThi);
    cudaGetSymbolAddress((void**)&peTlo, g_eTlo);
    cudaGetSymbolAddress((void**)&pwThi, g_wThi);
    cudaGetSymbolAddress((void**)&pwTlo, g_wTlo);

    cudaFuncSetAttribute(gemm1_kernel, cudaFuncAttributeMaxDynamicSharedMemorySize, G1_SMEM);
    cudaFuncSetAttribute(gemm2_kernel, cudaFuncAttributeMaxDynamicSharedMemorySize, G2_SMEM);

    // 0) one-time weight reshapes
    convT_kernel<<<dim3(KV_PAD / 32, NBP / 32, 2), dim3(32, 32)>>>(
        em1, em2, NV, NE, NE, KV_PAD, NBP, peThi, peTlo, (size_t)NBP * KV_PAD);
    convT_kernel<<<dim3(KE_PAD / 32, G4H / 32, 2), dim3(32, 32)>>>(
        Wl1, Wl2, NE, G4H, G4H, KE_PAD, G4H, pwThi, pwTlo, (size_t)G4H * KE_PAD);

    // 1) embeddings: e = X @ embed   (368 CTAs, 2/SM, 3-stage 1-barrier pipe)
    gemm1_kernel<<<dim3(NBP / 80, NM / 128, 2), 256, G1_SMEM>>>(
        x1, x2, peThi, peTlo, pehi, pelo);

    // 2) gate preactivations: xz = e @ W[:300]
    gemm2_kernel<<<dim3(NM / 128, 4, 2), 256, G2_SMEM>>>(
        pehi, pelo, pwThi, pwTlo, pxz);

    // 3) sequential LSTM recurrence
    lstm_kernel<<<dim3(NB / 4, 2), 512>>>(Wl1, Wl2, lng1, lnb1, lng2, lnb2);

    // 4) attention + fc1
    attn_fc1_kernel<<<dim3(NB, 2), 512>>>(v1, Wo1, bo1, v2, Wo2, bo2);

    // 5) fc2 + logits
    fc23_kernel<<<NB / 4, 512>>>(Wh, bh, Wout, bout, out);
}

// round 14
// speedup vs baseline: 1.0015x; 1.0015x over previous
#include <cuda_runtime.h>
#include <cuda_bf16.h>
#include <math.h>
#include <cstdint>

// ---------------- problem constants ----------------
constexpr int NB = 128;      // batch
constexpr int NT_STEPS = 46; // time steps
constexpr int NV = 8150;     // vocab
constexpr int NE = 300;      // embed dim
constexpr int NH = 128;      // lstm hidden
constexpr int NM = NB * NT_STEPS;  // 5888 rows
constexpr int G4H = 512;     // 4*H
constexpr int KV_PAD = 8192; // vocab K padded
constexpr int NBP = 320;     // embed out cols padded
constexpr int KE_PAD = 320;  // GEMM2 K

// ---------------- device scratch ----------------
__device__ __nv_bfloat16 g_ehi[2 * NM * NBP];
__device__ __nv_bfloat16 g_elo[2 * NM * NBP];
__device__ float g_xz[2 * NM * G4H];
__device__ float g_o [2 * NB * NT_STEPS * NH];
__device__ float g_a [NB * 1024];
__device__ __nv_bfloat16 g_eThi[2 * NBP * KV_PAD];
__device__ __nv_bfloat16 g_eTlo[2 * NBP * KV_PAD];
__device__ __nv_bfloat16 g_wThi[2 * G4H * KE_PAD];
__device__ __nv_bfloat16 g_wTlo[2 * G4H * KE_PAD];

__device__ __forceinline__ float sigmoidf(float x) { return 1.f / (1.f + expf(-x)); }

// ================= helpers =================
__device__ __forceinline__ void cpasync16(uint32_t dst, const void* src) {
    asm volatile("cp.async.cg.shared.global [%0], [%1], 16;" :: "r"(dst), "l"(src));
}
__device__ __forceinline__ uint32_t smem_u32(const void* p) {
    uint32_t a;
    asm("{ .reg .u64 t; cvta.to.shared.u64 t, %1; cvt.u32.u64 %0, t; }" : "=r"(a) : "l"(p));
    return a;
}
#define CP_COMMIT() asm volatile("cp.async.commit_group;" ::: "memory")
#define CP_WAIT0()  asm volatile("cp.async.wait_group 0;" ::: "memory")
#define CP_WAIT1()  asm volatile("cp.async.wait_group 1;" ::: "memory")
#define CP_WAIT2()  asm volatile("cp.async.wait_group 2;" ::: "memory")

__device__ __forceinline__ uint32_t pack_bf16(float a, float b) {
    __nv_bfloat16 ha = __float2bfloat16(a), hb = __float2bfloat16(b);
    return (uint32_t)__bfloat16_as_ushort(ha) | ((uint32_t)__bfloat16_as_ushort(hb) << 16);
}

__device__ __forceinline__ void mma16816(float* c, const uint32_t* a, uint32_t b0, uint32_t b1) {
    asm volatile(
        "mma.sync.aligned.m16n8k16.row.col.f32.bf16.bf16.f32 "
        "{%0,%1,%2,%3},{%4,%5,%6,%7},{%8,%9},{%0,%1,%2,%3};"
        : "+f"(c[0]), "+f"(c[1]), "+f"(c[2]), "+f"(c[3])
        : "r"(a[0]), "r"(a[1]), "r"(a[2]), "r"(a[3]), "r"(b0), "r"(b1));
}

// smem tile geometry: K-chunk 32 elems, row stride 40 elems (80B: 16B-aligned,
// 20-bank shift per row -> conflict-free fragment loads)
constexpr int KST = 40;

// 3-pass split MMA over one staged 32-K chunk (R10 order: each B fragment
// loaded once; 3 MMAs per (i,j) issued together).
template<int MFRAG, int NFRAG>
__device__ __forceinline__ void compute_chunk(
    const char* AH, const char* AL, const char* BH, const char* BL,
    int wm, int wn, int qrow, int qcol, float (*c)[NFRAG][4])
{
#pragma unroll
    for (int kk = 0; kk < 32; kk += 16) {
        uint32_t ah[MFRAG][4], al[MFRAG][4];
#pragma unroll
        for (int i = 0; i < MFRAG; i++) {
            int r = wm + i * 16 + qrow;
            const char* pH = AH + (size_t)(r * KST + kk + qcol) * 2;
            const char* pL = AL + (size_t)(r * KST + kk + qcol) * 2;
            ah[i][0] = *(const uint32_t*)pH;
            ah[i][1] = *(const uint32_t*)(pH + 8 * KST * 2);
            ah[i][2] = *(const uint32_t*)(pH + 16);
            ah[i][3] = *(const uint32_t*)(pH + 8 * KST * 2 + 16);
            al[i][0] = *(const uint32_t*)pL;
            al[i][1] = *(const uint32_t*)(pL + 8 * KST * 2);
            al[i][2] = *(const uint32_t*)(pL + 16);
            al[i][3] = *(const uint32_t*)(pL + 8 * KST * 2 + 16);
        }
#pragma unroll
        for (int j = 0; j < NFRAG; j++) {
            int n = wn + j * 8 + qrow;
            const char* qH = BH + (size_t)(n * KST + kk + qcol) * 2;
            const char* qL = BL + (size_t)(n * KST + kk + qcol) * 2;
            uint32_t bh0 = *(const uint32_t*)qH, bh1 = *(const uint32_t*)(qH + 16);
            uint32_t bl0 = *(const uint32_t*)qL, bl1 = *(const uint32_t*)(qL + 16);
#pragma unroll
            for (int i = 0; i < MFRAG; i++) {
                mma16816(c[i][j], ah[i], bh0, bh1);
                mma16816(c[i][j], ah[i], bl0, bl1);
                mma16816(c[i][j], al[i], bh0, bh1);
            }
        }
    }
}

// =====================================================================
// Transpose + bf16 hi/lo split:  D[n][k] = split(src[k][n]) zero-padded.
// =====================================================================
__global__ void convT_kernel(const float* __restrict__ S0, const float* __restrict__ S1,
                             int Rvalid, int Cvalid, int ld, int KPAD, int NTOT,
                             __nv_bfloat16* __restrict__ Dhi, __nv_bfloat16* __restrict__ Dlo,
                             size_t dstride)
{
    int s = blockIdx.z;
    const float* S = s ? S1 : S0;
    __nv_bfloat16* dh = Dhi + (size_t)s * dstride;
    __nv_bfloat16* dl = Dlo + (size_t)s * dstride;
    __shared__ float tile[32][33];
    int tx = threadIdx.x, ty = threadIdx.y;
    int gk = blockIdx.x * 32 + ty;
    int gn = blockIdx.y * 32 + tx;
    tile[ty][tx] = (gk < Rvalid && gn < Cvalid) ? S[(size_t)gk * ld + gn] : 0.f;
    __syncthreads();
    int k2 = blockIdx.x * 32 + tx;
    int n2 = blockIdx.y * 32 + ty;
    if (n2 < NTOT) {
        float v = tile[tx][ty];
        __nv_bfloat16 h = __float2bfloat16(v);
        __nv_bfloat16 l = __float2bfloat16(v - __bfloat162float(h));
        dh[(size_t)n2 * KPAD + k2] = h;
        dl[(size_t)n2 * KPAD + k2] = l;
    }
}

// =====================================================================
// GEMM1: e = X @ embed. Block 128x80, 256 thr, 8 warps (32x40, 4m x 2n).
// K-chunk 32, 3-stage cp.async pipeline, ONE barrier per chunk,
// R10 compute order. Grid (4 n, 46 m, 2 s) = 368 CTAs, 2/SM.
// =====================================================================
constexpr int G1_A = 128 * KST * 2;   // 10240 per operand per stage
constexpr int G1_B = 80 * KST * 2;    // 6400
constexpr int G1_STAGE = 2 * G1_A + 2 * G1_B;  // 33280
constexpr int G1_SMEM = 3 * G1_STAGE;          // 99840

__global__ void __launch_bounds__(256, 2) gemm1_kernel(
    const float* __restrict__ X0, const float* __restrict__ X1,
    const __nv_bfloat16* __restrict__ BTh, const __nv_bfloat16* __restrict__ BTl,
    __nv_bfloat16* __restrict__ Eh, __nv_bfloat16* __restrict__ El)
{
    extern __shared__ char sm[];
    const int s = blockIdx.z;
    const float* A = s ? X1 : X0;
    const __nv_bfloat16* bth = BTh + (size_t)s * NBP * KV_PAD;
    const __nv_bfloat16* btl = BTl + (size_t)s * NBP * KV_PAD;
    __nv_bfloat16* eh = Eh + (size_t)s * NM * NBP;
    __nv_bfloat16* el = El + (size_t)s * NM * NBP;
    const int m0 = blockIdx.y * 128;
    const int n0 = blockIdx.x * 80;

    const uint32_t sb = smem_u32(sm);
    const int tid = threadIdx.x;
    const int lane = tid & 31, warp = tid >> 5;
    const int wm = (warp >> 1) * 32, wn = (warp & 1) * 40;
    const int qrow = lane >> 2, qcol = (lane & 3) * 2;
    const int arow = tid >> 1, akb = (tid & 1) * 16;

    auto stageB = [&](int it, int buf) {
        const int k0 = it * 32;
        uint32_t base = sb + buf * G1_STAGE + 2 * G1_A;
        for (int x = tid; x < 640; x += 256) {
            int row = x >> 3, rem = x & 7;
            int half = rem >> 2, seg = rem & 3;
            const __nv_bfloat16* src = (half ? btl : bth)
                + (size_t)(n0 + row) * KV_PAD + k0 + seg * 8;
            uint32_t so = base + half * G1_B + (uint32_t)(row * 80 + seg * 16);
            cpasync16(so, src);
        }
    };
    auto loadA = [&](int it, float* v) {
        const int k0 = it * 32;
        const float* p = A + (size_t)(m0 + arow) * NV + k0 + akb;
        if (k0 + 32 <= NV) {
#pragma unroll
            for (int j = 0; j < 8; j++) { float2 t = ((const float2*)p)[j]; v[2*j] = t.x; v[2*j+1] = t.y; }
        } else {
#pragma unroll
            for (int j = 0; j < 16; j++) { int gk = k0 + akb + j; v[j] = (gk < NV) ? p[j] : 0.f; }
        }
    };
    auto storeA = [&](int buf, const float* v) {
        uint32_t hi[8], lo[8];
#pragma unroll
        for (int j = 0; j < 8; j++) {
            float v0 = v[2*j], v1 = v[2*j+1];
            float h0 = __bfloat162float(__float2bfloat16(v0));
            float h1 = __bfloat162float(__float2bfloat16(v1));
            hi[j] = pack_bf16(v0, v1);
            lo[j] = pack_bf16(v0 - h0, v1 - h1);
        }
        char* dH = sm + buf * G1_STAGE + arow * 80 + akb * 2;
        char* dL = dH + G1_A;
        *(uint4*)(dH)      = *(uint4*)(hi);
        *(uint4*)(dH + 16) = *(uint4*)(hi + 4);
        *(uint4*)(dL)      = *(uint4*)(lo);
        *(uint4*)(dL + 16) = *(uint4*)(lo + 4);
    };

    // ---- prologue: fill stages 0 and 1 ----
    stageB(0, 0); CP_COMMIT();
    stageB(1, 1); CP_COMMIT();
    {
        float v[16];
        loadA(0, v); storeA(0, v);
        loadA(1, v); storeA(1, v);
    }
    CP_WAIT1();           // stage 0 B complete
    __syncthreads();

    float c[2][5][4];
#pragma unroll
    for (int i = 0; i < 2; i++)
#pragma unroll
        for (int j = 0; j < 5; j++)
#pragma unroll
            for (int r = 0; r < 4; r++) c[i][j][r] = 0.f;

    const int iters = KV_PAD / 32;  // 256
    float vp[16];
    for (int it = 0; it < iters; ++it) {
        const int cur = it % 3;
        const bool pf = (it + 2 < iters);
        if (pf) {
            stageB(it + 2, (it + 2) % 3); CP_COMMIT();   // buffer last read at it-1
            loadA(it + 2, vp);
        }
        if (pf) { CP_WAIT2(); } else { CP_WAIT0(); }     // chunk it's B complete
        const char* base = sm + cur * G1_STAGE;
        compute_chunk<2, 5>(base, base + G1_A, base + 2 * G1_A, base + 2 * G1_A + G1_B,
                            wm, wn, qrow, qcol, c);
        if (pf) storeA((it + 2) % 3, vp);                // off critical path
        __syncthreads();                                 // single barrier per chunk
    }

    // epilogue: write e hi/lo
#pragma unroll
    for (int i = 0; i < 2; i++) {
        int r0 = m0 + wm + i * 16 + qrow;
#pragma unroll
        for (int j = 0; j < 5; j++) {
            int col = n0 + wn + j * 8 + qcol;
            float v0 = c[i][j][0], v1 = c[i][j][1];
            float h0 = __bfloat162float(__float2bfloat16(v0));
            float h1 = __bfloat162float(__float2bfloat16(v1));
            *(uint32_t*)&eh[(size_t)r0 * NBP + col] = pack_bf16(v0, v1);
            *(uint32_t*)&el[(size_t)r0 * NBP + col] = pack_bf16(v0 - h0, v1 - h1);
            float v2 = c[i][j][2], v3 = c[i][j][3];
            float h2 = __bfloat162float(__float2bfloat16(v2));
            float h3 = __bfloat162float(__float2bfloat16(v3));
            *(uint32_t*)&eh[(size_t)(r0 + 8) * NBP + col] = pack_bf16(v2, v3);
            *(uint32_t*)&el[(size_t)(r0 + 8) * NBP + col] = pack_bf16(v2 - h2, v3 - h3);
        }
    }
}

// =====================================================================
// GEMM2 (R10 exact): xz = e @ W[:300]. Block 128x128, 256 thr,
// warp 64x32 (2m x 4n). K-chunk 32, 3-stage.
// =====================================================================
constexpr int G2_BUF = 128 * KST * 2;    // 10240
constexpr int G2_SMEM = 3 * 4 * G2_BUF;  // 122880

__global__ void __launch_bounds__(256, 1) gemm2_kernel(
    const __nv_bfloat16* __restrict__ Eh, const __nv_bfloat16* __restrict__ El,
    const __nv_bfloat16* __restrict__ Wh, const __nv_bfloat16* __restrict__ Wl,
    float* __restrict__ XZ)
{
    extern __shared__ char sm[];
    const int s = blockIdx.z;
    const __nv_bfloat16* ah = Eh + (size_t)s * NM * NBP;
    const __nv_bfloat16* al = El + (size_t)s * NM * NBP;
    const __nv_bfloat16* bh = Wh + (size_t)s * G4H * KE_PAD;
    const __nv_bfloat16* bl = Wl + (size_t)s * G4H * KE_PAD;
    float* xz = XZ + (size_t)s * NM * G4H;
    const int m0 = blockIdx.x * 128;
    const int n0 = blockIdx.y * 128;

    const uint32_t sb = smem_u32(sm);
    char* AHb = sm;
    char* ALb = sm + 3 * G2_BUF;
    char* BHb = sm + 6 * G2_BUF;
    char* BLb = sm + 9 * G2_BUF;

    const int tid = threadIdx.x;
    const int lane = tid & 31, warp = tid >> 5;
    const int wm = (warp >> 2) * 64, wn = (warp & 3) * 32;
    const int qrow = lane >> 2, qcol = (lane & 3) * 2;

    auto stage = [&](int it, int buf) {
        const int k0 = it * 32;
        uint32_t dAH = sb + (uint32_t)(AHb - sm) + buf * G2_BUF;
        uint32_t dAL = sb + (uint32_t)(ALb - sm) + buf * G2_BUF;
        uint32_t dBH = sb + (uint32_t)(BHb - sm) + buf * G2_BUF;
        uint32_t dBL = sb + (uint32_t)(BLb - sm) + buf * G2_BUF;
#pragma unroll
        for (int x = tid; x < 512; x += 256) {
            int row = x >> 2, seg = x & 3;
            uint32_t so = (uint32_t)(row * KST + seg * 8) * 2;
            size_t ga = (size_t)(m0 + row) * NBP + k0 + seg * 8;
            size_t gb = (size_t)(n0 + row) * KE_PAD + k0 + seg * 8;
            cpasync16(dAH + so, ah + ga);
            cpasync16(dAL + so, al + ga);
            cpasync16(dBH + so, bh + gb);
            cpasync16(dBL + so, bl + gb);
        }
    };

    stage(0, 0); CP_COMMIT();
    stage(1, 1); CP_COMMIT();
    CP_WAIT0();
    __syncthreads();

    float c[4][4][4];
#pragma unroll
    for (int i = 0; i < 4; i++)
#pragma unroll
        for (int j = 0; j < 4; j++)
#pragma unroll
            for (int r = 0; r < 4; r++) c[i][j][r] = 0.f;

    const int iters = KE_PAD / 32;  // 10
    for (int it = 0; it < iters; ++it) {
        const int cur = it % 3;
        const bool pf = (it + 2 < iters);
        if (pf) { stage(it + 2, (it + 2) % 3); CP_COMMIT(); }
        if (pf) { CP_WAIT1(); } else { CP_WAIT0(); }
        compute_chunk<4, 4>(AHb + cur * G2_BUF, ALb + cur * G2_BUF,
                            BHb + cur * G2_BUF, BLb + cur * G2_BUF,
                            wm, wn, qrow, qcol, c);
        __syncthreads();
    }

#pragma unroll
    for (int i = 0; i < 4; i++) {
        int r0 = m0 + wm + i * 16 + qrow;
#pragma unroll
        for (int j = 0; j < 4; j++) {
            int col = n0 + wn + j * 8 + qcol;
            *(float2*)&xz[(size_t)r0 * G4H + col]       = make_float2(c[i][j][0], c[i][j][1]);
            *(float2*)&xz[(size_t)(r0 + 8) * G4H + col] = make_float2(c[i][j][2], c[i][j][3]);
        }
    }
}

// =====================================================================
// LSTM recurrence (R6 version: scalar coalesced Wr reads).
// =====================================================================
__global__ void __launch_bounds__(512) lstm_kernel(
    const float* __restrict__ Wl1, const float* __restrict__ Wl2,
    const float* __restrict__ lng1, const float* __restrict__ lnb1,
    const float* __restrict__ lng2, const float* __restrict__ lnb2)
{
    int s = blockIdx.y;
    const float* Wr  = (s ? Wl2 : Wl1) + NE * G4H;
    const float* lng = s ? lng2 : lng1;
    const float* lnb = s ? lnb2 : lnb1;
    const float* xz  = g_xz + (size_t)s * NM * G4H;

    int b0   = blockIdx.x * 4;
    int col  = threadIdx.x;
    int w    = threadIdx.x >> 5;
    int lane = threadIdx.x & 31;
    int rrl  = threadIdx.x >> 7;
    int idx  = threadIdx.x & 127;

    __shared__ float h_sh[4][128];
    __shared__ float zbuf[4][512];
    __shared__ float mu_s[4][4], rstd_s[4][4];
    __shared__ float wp1[16], wp2[16];

    h_sh[rrl][idx] = 0.f;
    float c_val = 0.f;

    float gi = lng[idx],       gj = lng[128 + idx], gf = lng[256 + idx];
    float go = lng[384 + idx], gc = lng[512 + idx];
    float bi = lnb[idx],       bj = lnb[128 + idx], bf = lnb[256 + idx];
    float bo = lnb[384 + idx], bc = lnb[512 + idx];
    __syncthreads();

    for (int t = 0; t < NT_STEPS; t++) {
        float a0 = xz[(size_t)((b0 + 0) * NT_STEPS + t) * G4H + col];
        float a1 = xz[(size_t)((b0 + 1) * NT_STEPS + t) * G4H + col];
        float a2 = xz[(size_t)((b0 + 2) * NT_STEPS + t) * G4H + col];
        float a3 = xz[(size_t)((b0 + 3) * NT_STEPS + t) * G4H + col];

#pragma unroll 8
        for (int k = 0; k < NH; k += 4) {
            float4 h0 = *(const float4*)&h_sh[0][k];
            float4 h1 = *(const float4*)&h_sh[1][k];
            float4 h2 = *(const float4*)&h_sh[2][k];
            float4 h3 = *(const float4*)&h_sh[3][k];
            float w0 = Wr[(k + 0) * G4H + col];
            float w1 = Wr[(k + 1) * G4H + col];
            float w2 = Wr[(k + 2) * G4H + col];
            float w3 = Wr[(k + 3) * G4H + col];
            a0 = fmaf(h0.x, w0, fmaf(h0.y, w1, fmaf(h0.z, w2, fmaf(h0.w, w3, a0))));
            a1 = fmaf(h1.x, w0, fmaf(h1.y, w1, fmaf(h1.z, w2, fmaf(h1.w, w3, a1))));
            a2 = fmaf(h2.x, w0, fmaf(h2.y, w1, fmaf(h2.z, w2, fmaf(h2.w, w3, a2))));
            a3 = fmaf(h3.x, w0, fmaf(h3.y, w1, fmaf(h3.z, w2, fmaf(h3.w, w3, a3))));
        }
        zbuf[0][col] = a0; zbuf[1][col] = a1; zbuf[2][col] = a2; zbuf[3][col] = a3;
        __syncthreads();

        {
            int rr = w >> 2, gg = w & 3;
            float s1 = 0.f, s2 = 0.f;
#pragma unroll
            for (int i = 0; i < 4; i++) {
                float v = zbuf[rr][gg * 128 + lane + 32 * i];
                s1 += v;
                s2 = fmaf(v, v, s2);
            }
#pragma unroll
            for (int off = 16; off; off >>= 1) {
                s1 += __shfl_xor_sync(0xffffffffu, s1, off);
                s2 += __shfl_xor_sync(0xffffffffu, s2, off);
            }
            if (lane == 0) {
                float mu  = s1 * (1.f / 128.f);
                float var = fmaxf(s2 * (1.f / 128.f) - mu * mu, 0.f);
                mu_s[rr][gg]   = mu;
                rstd_s[rr][gg] = rsqrtf(var + 1e-12f);
            }
        }
        __syncthreads();

        int r = rrl;
        float zi = (zbuf[r][idx]       - mu_s[r][0]) * rstd_s[r][0] * gi + bi;
        float zj = (zbuf[r][128 + idx] - mu_s[r][1]) * rstd_s[r][1] * gj + bj;
        float zf = (zbuf[r][256 + idx] - mu_s[r][2]) * rstd_s[r][2] * gf + bf;
        float zo = (zbuf[r][384 + idx] - mu_s[r][3]) * rstd_s[r][3] * go + bo;
        float cn = c_val * sigmoidf(zf + 1.f) + sigmoidf(zi) * fmaxf(zj, 0.f);
        c_val = cn;

        float s1 = cn, s2 = cn * cn;
#pragma unroll
        for (int off = 16; off; off >>= 1) {
            s1 += __shfl_xor_sync(0xffffffffu, s1, off);
            s2 += __shfl_xor_sync(0xffffffffu, s2, off);
        }
        if (lane == 0) { wp1[w] = s1; wp2[w] = s2; }
        __syncthreads();
        float ss1 = wp1[4 * r] + wp1[4 * r + 1] + wp1[4 * r + 2] + wp1[4 * r + 3];
        float ss2 = wp2[4 * r] + wp2[4 * r + 1] + wp2[4 * r + 2] + wp2[4 * r + 3];
        float mu_c   = ss1 * (1.f / 128.f);
        float var_c  = fmaxf(ss2 * (1.f / 128.f) - mu_c * mu_c, 0.f);
        float rstd_c = rsqrtf(var_c + 1e-12f);

        float hn = fmaxf((cn - mu_c) * rstd_c * gc + bc, 0.f) * sigmoidf(zo);
        h_sh[r][idx] = hn;
        g_o[(((size_t)s * NB + b0 + r) * NT_STEPS + t) * NH + idx] = hn;
        __syncthreads();
    }
}

// =====================================================================
// Attention + fc1.
// =====================================================================
__global__ void __launch_bounds__(512) attn_fc1_kernel(
    const float* __restrict__ v1, const float* __restrict__ Wo1, const float* __restrict__ bo1,
    const float* __restrict__ v2, const float* __restrict__ Wo2, const float* __restrict__ bo2)
{
    int s = blockIdx.y, b = blockIdx.x;
    const float* vv = s ? v2  : v1;
    const float* Wo = s ? Wo2 : Wo1;
    const float* bo = s ? bo2 : bo1;
    const float* ob = g_o + ((size_t)(s * NB + b) * NT_STEPS) * NH;

    __shared__ float sc[64];
    __shared__ float ctx[128];
    int w = threadIdx.x >> 5, lane = threadIdx.x & 31;

    for (int t = w; t < NT_STEPS; t += 16) {
        float p = 0.f;
#pragma unroll
        for (int i = 0; i < 4; i++)
            p = fmaf(ob[t * NH + lane + 32 * i], vv[lane + 32 * i], p);
#pragma unroll
        for (int off = 16; off; off >>= 1) p += __shfl_xor_sync(0xffffffffu, p, off);
        if (lane == 0) sc[t] = p;
    }
    __syncthreads();

    if (w == 0) {
        float v0 = sc[lane];
        float vb = (lane + 32 < NT_STEPS) ? sc[lane + 32] : -1e30f;
        float mx = fmaxf(v0, vb);
#pragma unroll
        for (int off = 16; off; off >>= 1) mx = fmaxf(mx, __shfl_xor_sync(0xffffffffu, mx, off));
        float e0 = expf(v0 - mx);
        float e1 = (lane + 32 < NT_STEPS) ? expf(vb - mx) : 0.f;
        float sm = e0 + e1;
#pragma unroll
        for (int off = 16; off; off >>= 1) sm += __shfl_xor_sync(0xffffffffu, sm, off);
        float inv = 1.f / sm;
        sc[lane] = e0 * inv;
        if (lane + 32 < NT_STEPS) sc[lane + 32] = e1 * inv;
    }
    __syncthreads();

    if (threadIdx.x < NH) {
        float p = 0.f;
        for (int t = 0; t < NT_STEPS; t++) p = fmaf(sc[t], ob[t * NH + threadIdx.x], p);
        ctx[threadIdx.x] = p;
    }
    __syncthreads();

    int j = threadIdx.x;
    float accv = bo[j];
#pragma unroll 4
    for (int h = 0; h < NH; h++) accv = fmaf(ctx[h], Wo[h * 512 + j], accv);
    g_a[(size_t)b * 1024 + s * 512 + j] = fmaxf(accv, 0.f);
}

// =====================================================================
// fc2 + fc3.
// =====================================================================
__global__ void __launch_bounds__(512) fc23_kernel(
    const float* __restrict__ Wh, const float* __restrict__ bh,
    const float* __restrict__ Wout, const float* __restrict__ bout,
    float* __restrict__ out)
{
    int b0 = blockIdx.x * 4;
    __shared__ float a_sh[4][1024];
    __shared__ float hid[4][512];
    int tid = threadIdx.x;

#pragma unroll
    for (int p = 0; p < 8; p++) {
        int i = p * 512 + tid;
        a_sh[i >> 10][i & 1023] = g_a[(size_t)b0 * 1024 + i];
    }
    __syncthreads();

    float acc0 = bh[tid], acc1 = bh[tid], acc2 = bh[tid], acc3 = bh[tid];
    for (int k = 0; k < 1024; k++) {
        float wv = Wh[k * 512 + tid];
        acc0 = fmaf(a_sh[0][k], wv, acc0);
        acc1 = fmaf(a_sh[1][k], wv, acc1);
        acc2 = fmaf(a_sh[2][k], wv, acc2);
        acc3 = fmaf(a_sh[3][k], wv, acc3);
    }
    hid[0][tid] = fmaxf(acc0, 0.f);
    hid[1][tid] = fmaxf(acc1, 0.f);
    hid[2][tid] = fmaxf(acc2, 0.f);
    hid[3][tid] = fmaxf(acc3, 0.f);
    __syncthreads();

    int w = tid >> 5, lane = tid & 31;
    if (w < 8) {
        int r = w >> 1, oc = w & 1;
        float p = 0.f;
#pragma unroll
        for (int i = 0; i < 16; i++) {
            int k = lane + 32 * i;
            p = fmaf(hid[r][k], Wout[k * 2 + oc], p);
        }
#pragma unroll
        for (int off = 16; off; off >>= 1) p += __shfl_xor_sync(0xffffffffu, p, off);
        if (lane == 0) out[(b0 + r) * 2 + oc] = p + bout[oc];
    }
}

// =====================================================================
extern "C" void kernel_launch(void* const* d_in, const int* in_sizes, int n_in,
                              void* d_out, int out_size)
{
    const float* x1   = (const float*)d_in[0];
    const float* x2   = (const float*)d_in[1];
    const float* em1  = (const float*)d_in[2];
    const float* em2  = (const float*)d_in[3];
    const float* Wl1  = (const float*)d_in[4];
    const float* Wl2  = (const float*)d_in[5];
    const float* lng1 = (const float*)d_in[6];
    const float* lnb1 = (const float*)d_in[7];
    const float* lng2 = (const float*)d_in[8];
    const float* lnb2 = (const float*)d_in[9];
    const float* v1   = (const float*)d_in[10];
    const float* Wo1  = (const float*)d_in[11];
    const float* bo1  = (const float*)d_in[12];
    const float* v2   = (const float*)d_in[13];
    const float* Wo2  = (const float*)d_in[14];
    const float* bo2  = (const float*)d_in[15];
    const float* Wh   = (const float*)d_in[16];
    const float* bh   = (const float*)d_in[17];
    const float* Wout = (const float*)d_in[18];
    const float* bout = (const float*)d_in[19];
    float* out = (float*)d_out;

    float *pxz;
    __nv_bfloat16 *pehi, *pelo, *peThi, *peTlo, *pwThi, *pwTlo;
    cudaGetSymbolAddress((void**)&pxz,   g_xz);
    cudaGetSymbolAddress((void**)&pehi,  g_ehi);
    cudaGetSymbolAddress((void**)&pelo,  g_elo);
    cudaGetSymbolAddress((void**)&peThi, g_eThi);
    cudaGetSymbolAddress((void**)&peTlo, g_eTlo);
    cudaGetSymbolAddress((void**)&pwThi, g_wThi);
    cudaGetSymbolAddress((void**)&pwTlo, g_wTlo);

    cudaFuncSetAttribute(gemm1_kernel, cudaFuncAttributeMaxDynamicSharedMemorySize, G1_SMEM);
    cudaFuncSetAttribute(gemm2_kernel, cudaFuncAttributeMaxDynamicSharedMemorySize, G2_SMEM);

    // 0) one-time weight reshapes
    convT_kernel<<<dim3(KV_PAD / 32, NBP / 32, 2), dim3(32, 32)>>>(
        em1, em2, NV, NE, NE, KV_PAD, NBP, peThi, peTlo, (size_t)NBP * KV_PAD);
    convT_kernel<<<dim3(KE_PAD / 32, G4H / 32, 2), dim3(32, 32)>>>(
        Wl1, Wl2, NE, G4H, G4H, KE_PAD, G4H, pwThi, pwTlo, (size_t)G4H * KE_PAD);

    // 1) embeddings: e = X @ embed   (368 CTAs, 2/SM, 3-stage 1-barrier pipe,
    //    R10 compute order)
    gemm1_kernel<<<dim3(NBP / 80, NM / 128, 2), 256, G1_SMEM>>>(
        x1, x2, peThi, peTlo, pehi, pelo);

    // 2) gate preactivations: xz = e @ W[:300]
    gemm2_kernel<<<dim3(NM / 128, 4, 2), 256, G2_SMEM>>>(
        pehi, pelo, pwThi, pwTlo, pxz);

    // 3) sequential LSTM recurrence
    lstm_kernel<<<dim3(NB / 4, 2), 512>>>(Wl1, Wl2, lng1, lnb1, lng2, lnb2);

    // 4) attention + fc1
    attn_fc1_kernel<<<dim3(NB, 2), 512>>>(v1, Wo1, bo1, v2, Wo2, bo2);

    // 5) fc2 + logits
    fc23_kernel<<<NB / 4, 512>>>(Wh, bh, Wout, bout, out);
}

// round 15
// speedup vs baseline: 1.2896x; 1.2876x over previous
#include <cuda_runtime.h>
#include <cuda_bf16.h>
#include <math.h>
#include <cstdint>

// ---------------- problem constants ----------------
constexpr int NB = 128;      // batch
constexpr int NT_STEPS = 46; // time steps
constexpr int NV = 8150;     // vocab
constexpr int NE = 300;      // embed dim
constexpr int NH = 128;      // lstm hidden
constexpr int NM = NB * NT_STEPS;  // 5888 rows
constexpr int G4H = 512;     // 4*H
constexpr int KV_PAD = 8192; // vocab K padded
constexpr int NBP = 320;     // embed out cols padded
constexpr int KE_PAD = 320;  // GEMM2 K

// ---------------- device scratch ----------------
__device__ __nv_bfloat16 g_ehi[2 * NM * NBP];
__device__ __nv_bfloat16 g_elo[2 * NM * NBP];
__device__ float g_xz[2 * NM * G4H];
__device__ float g_o [2 * NB * NT_STEPS * NH];
__device__ float g_a [NB * 1024];
__device__ __nv_bfloat16 g_eThi[2 * NBP * KV_PAD];
__device__ __nv_bfloat16 g_eTlo[2 * NBP * KV_PAD];
__device__ __nv_bfloat16 g_wThi[2 * G4H * KE_PAD];
__device__ __nv_bfloat16 g_wTlo[2 * G4H * KE_PAD];

__device__ __forceinline__ float sigmoidf(float x) { return 1.f / (1.f + expf(-x)); }

// ================= helpers =================
__device__ __forceinline__ void cpasync16(uint32_t dst, const void* src) {
    asm volatile("cp.async.cg.shared.global [%0], [%1], 16;" :: "r"(dst), "l"(src));
}
__device__ __forceinline__ uint32_t smem_u32(const void* p) {
    uint32_t a;
    asm("{ .reg .u64 t; cvta.to.shared.u64 t, %1; cvt.u32.u64 %0, t; }" : "=r"(a) : "l"(p));
    return a;
}
#define CP_COMMIT() asm volatile("cp.async.commit_group;" ::: "memory")
#define CP_WAIT0()  asm volatile("cp.async.wait_group 0;" ::: "memory")
#define CP_WAIT1()  asm volatile("cp.async.wait_group 1;" ::: "memory")

__device__ __forceinline__ uint32_t pack_bf16(float a, float b) {
    __nv_bfloat16 ha = __float2bfloat16(a), hb = __float2bfloat16(b);
    return (uint32_t)__bfloat16_as_ushort(ha) | ((uint32_t)__bfloat16_as_ushort(hb) << 16);
}

__device__ __forceinline__ void mma16816(float* c, const uint32_t* a, uint32_t b0, uint32_t b1) {
    asm volatile(
        "mma.sync.aligned.m16n8k16.row.col.f32.bf16.bf16.f32 "
        "{%0,%1,%2,%3},{%4,%5,%6,%7},{%8,%9},{%0,%1,%2,%3};"
        : "+f"(c[0]), "+f"(c[1]), "+f"(c[2]), "+f"(c[3])
        : "r"(a[0]), "r"(a[1]), "r"(a[2]), "r"(a[3]), "r"(b0), "r"(b1));
}

// smem tile geometry: K-chunk 32 elems, row stride 40 elems (80B: 16B-aligned,
// 20-bank shift per row -> conflict-free fragment loads)
constexpr int KST = 40;

// 3-pass split MMA over one staged 32-K chunk (each B fragment loaded once;
// 3 MMAs per (i,j) issued together).
template<int MFRAG, int NFRAG>
__device__ __forceinline__ void compute_chunk(
    const char* AH, const char* AL, const char* BH, const char* BL,
    int wm, int wn, int qrow, int qcol, float (*c)[NFRAG][4])
{
#pragma unroll
    for (int kk = 0; kk < 32; kk += 16) {
        uint32_t ah[MFRAG][4], al[MFRAG][4];
#pragma unroll
        for (int i = 0; i < MFRAG; i++) {
            int r = wm + i * 16 + qrow;
            const char* pH = AH + (size_t)(r * KST + kk + qcol) * 2;
            const char* pL = AL + (size_t)(r * KST + kk + qcol) * 2;
            ah[i][0] = *(const uint32_t*)pH;
            ah[i][1] = *(const uint32_t*)(pH + 8 * KST * 2);
            ah[i][2] = *(const uint32_t*)(pH + 16);
            ah[i][3] = *(const uint32_t*)(pH + 8 * KST * 2 + 16);
            al[i][0] = *(const uint32_t*)pL;
            al[i][1] = *(const uint32_t*)(pL + 8 * KST * 2);
            al[i][2] = *(const uint32_t*)(pL + 16);
            al[i][3] = *(const uint32_t*)(pL + 8 * KST * 2 + 16);
        }
#pragma unroll
        for (int j = 0; j < NFRAG; j++) {
            int n = wn + j * 8 + qrow;
            const char* qH = BH + (size_t)(n * KST + kk + qcol) * 2;
            const char* qL = BL + (size_t)(n * KST + kk + qcol) * 2;
            uint32_t bh0 = *(const uint32_t*)qH, bh1 = *(const uint32_t*)(qH + 16);
            uint32_t bl0 = *(const uint32_t*)qL, bl1 = *(const uint32_t*)(qL + 16);
#pragma unroll
            for (int i = 0; i < MFRAG; i++) {
                mma16816(c[i][j], ah[i], bh0, bh1);
                mma16816(c[i][j], ah[i], bl0, bl1);
                mma16816(c[i][j], al[i], bh0, bh1);
            }
        }
    }
}

// =====================================================================
// Transpose + bf16 hi/lo split:  D[n][k] = split(src[k][n]) zero-padded.
// =====================================================================
__global__ void convT_kernel(const float* __restrict__ S0, const float* __restrict__ S1,
                             int Rvalid, int Cvalid, int ld, int KPAD, int NTOT,
                             __nv_bfloat16* __restrict__ Dhi, __nv_bfloat16* __restrict__ Dlo,
                             size_t dstride)
{
    int s = blockIdx.z;
    const float* S = s ? S1 : S0;
    __nv_bfloat16* dh = Dhi + (size_t)s * dstride;
    __nv_bfloat16* dl = Dlo + (size_t)s * dstride;
    __shared__ float tile[32][33];
    int tx = threadIdx.x, ty = threadIdx.y;
    int gk = blockIdx.x * 32 + ty;
    int gn = blockIdx.y * 32 + tx;
    tile[ty][tx] = (gk < Rvalid && gn < Cvalid) ? S[(size_t)gk * ld + gn] : 0.f;
    __syncthreads();
    int k2 = blockIdx.x * 32 + tx;
    int n2 = blockIdx.y * 32 + ty;
    if (n2 < NTOT) {
        float v = tile[tx][ty];
        __nv_bfloat16 h = __float2bfloat16(v);
        __nv_bfloat16 l = __float2bfloat16(v - __bfloat162float(h));
        dh[(size_t)n2 * KPAD + k2] = h;
        dl[(size_t)n2 * KPAD + k2] = l;
    }
}

// =====================================================================
// GEMM1 (R7 version, measured 842us): e = X @ embed.
// Block 64x80, 128 thr, 4 warps (2m x 2n, warp 32x40). K-chunk 32,
// 3-buffer rotation, 2 barriers/chunk. Grid (4 n, 92 m, 2 s) = 736 CTAs.
// =====================================================================
constexpr int G1_AB = 64 * KST * 2;    // 5120 bytes per A stage (hi or lo)
constexpr int G1_BB = 80 * KST * 2;    // 6400
constexpr int G1_SMEM = 3 * (2 * G1_AB + 2 * G1_BB);  // 69120

__global__ void __launch_bounds__(128) gemm1_kernel(
    const float* __restrict__ X0, const float* __restrict__ X1,
    const __nv_bfloat16* __restrict__ BTh, const __nv_bfloat16* __restrict__ BTl,
    __nv_bfloat16* __restrict__ Eh, __nv_bfloat16* __restrict__ El)
{
    extern __shared__ char sm[];
    const int s = blockIdx.z;
    const float* A = s ? X1 : X0;
    const __nv_bfloat16* bth = BTh + (size_t)s * NBP * KV_PAD;
    const __nv_bfloat16* btl = BTl + (size_t)s * NBP * KV_PAD;
    __nv_bfloat16* eh = Eh + (size_t)s * NM * NBP;
    __nv_bfloat16* el = El + (size_t)s * NM * NBP;
    const int m0 = blockIdx.y * 64;
    const int n0 = blockIdx.x * 80;

    char* AHb = sm;
    char* ALb = sm + 3 * G1_AB;
    char* BHb = sm + 6 * G1_AB;
    char* BLb = sm + 6 * G1_AB + 3 * G1_BB;
    const uint32_t sb = smem_u32(sm);

    const int tid = threadIdx.x;
    const int lane = tid & 31, warp = tid >> 5;
    const int wm = (warp >> 1) * 32, wn = (warp & 1) * 40;
    const int qrow = lane >> 2, qcol = (lane & 3) * 2;
    const int arow = tid >> 1, akb = (tid & 1) * 16;

    auto stageB = [&](int it, int buf) {
        const int k0 = it * 32;
        uint32_t dH = sb + (uint32_t)(BHb - sm) + buf * G1_BB;
        uint32_t dL = sb + (uint32_t)(BLb - sm) + buf * G1_BB;
#pragma unroll
        for (int x = tid; x < 320; x += 128) {
            int row = x >> 2, seg = x & 3;
            size_t go = (size_t)(n0 + row) * KV_PAD + k0 + seg * 8;
            uint32_t so = (uint32_t)(row * KST + seg * 8) * 2;
            cpasync16(dH + so, bth + go);
            cpasync16(dL + so, btl + go);
        }
    };
    auto loadA = [&](int it, float* v) {
        const int k0 = it * 32;
        const float* p = A + (size_t)(m0 + arow) * NV + k0 + akb;
        if (k0 + 32 <= NV) {
#pragma unroll
            for (int j = 0; j < 8; j++) { float2 t = ((const float2*)p)[j]; v[2*j] = t.x; v[2*j+1] = t.y; }
        } else {
#pragma unroll
            for (int j = 0; j < 16; j++) { int gk = k0 + akb + j; v[j] = (gk < NV) ? p[j] : 0.f; }
        }
    };
    auto storeA = [&](int buf, const float* v) {
        char* dH = AHb + buf * G1_AB;
        char* dL = ALb + buf * G1_AB;
#pragma unroll
        for (int j = 0; j < 8; j++) {
            float v0 = v[2*j], v1 = v[2*j+1];
            float h0 = __bfloat162float(__float2bfloat16(v0));
            float h1 = __bfloat162float(__float2bfloat16(v1));
            uint32_t off = (uint32_t)(arow * KST + akb + 2*j) * 2;
            *(uint32_t*)(dH + off) = pack_bf16(v0, v1);
            *(uint32_t*)(dL + off) = pack_bf16(v0 - h0, v1 - h1);
        }
    };

    // prologue: stage chunks 0, 1
    stageB(0, 0); CP_COMMIT();
    stageB(1, 1); CP_COMMIT();
    {
        float v[16];
        loadA(0, v); storeA(0, v);
        loadA(1, v); storeA(1, v);
    }
    CP_WAIT0();
    __syncthreads();

    float c[2][5][4];
#pragma unroll
    for (int i = 0; i < 2; i++)
#pragma unroll
        for (int j = 0; j < 5; j++)
#pragma unroll
            for (int r = 0; r < 4; r++) c[i][j][r] = 0.f;

    const int iters = KV_PAD / 32;  // 256
    float vp[16];
    for (int it = 0; it < iters; ++it) {
        const int cur = it % 3;
        const bool pf = (it + 2 < iters);
        if (pf) {
            stageB(it + 2, (it + 2) % 3); CP_COMMIT();
            loadA(it + 2, vp);
        }
        if (pf) { CP_WAIT1(); } else { CP_WAIT0(); }
        compute_chunk<2, 5>(AHb + cur * G1_AB, ALb + cur * G1_AB,
                            BHb + cur * G1_BB, BLb + cur * G1_BB,
                            wm, wn, qrow, qcol, c);
        __syncthreads();
        if (pf) storeA((it + 2) % 3, vp);
    }

    // epilogue: write e hi/lo
#pragma unroll
    for (int i = 0; i < 2; i++) {
        int r0 = m0 + wm + i * 16 + qrow;
#pragma unroll
        for (int j = 0; j < 5; j++) {
            int col = n0 + wn + j * 8 + qcol;
            float v0 = c[i][j][0], v1 = c[i][j][1];
            float h0 = __bfloat162float(__float2bfloat16(v0));
            float h1 = __bfloat162float(__float2bfloat16(v1));
            *(uint32_t*)&eh[(size_t)r0 * NBP + col] = pack_bf16(v0, v1);
            *(uint32_t*)&el[(size_t)r0 * NBP + col] = pack_bf16(v0 - h0, v1 - h1);
            float v2 = c[i][j][2], v3 = c[i][j][3];
            float h2 = __bfloat162float(__float2bfloat16(v2));
            float h3 = __bfloat162float(__float2bfloat16(v3));
            *(uint32_t*)&eh[(size_t)(r0 + 8) * NBP + col] = pack_bf16(v2, v3);
            *(uint32_t*)&el[(size_t)(r0 + 8) * NBP + col] = pack_bf16(v2 - h2, v3 - h3);
        }
    }
}

// =====================================================================
// GEMM2 (R10 exact, measured 52us): xz = e @ W[:300]. Block 128x128,
// 256 thr, warp 64x32 (2m x 4n). K-chunk 32, 3-stage.
// =====================================================================
constexpr int G2_BUF = 128 * KST * 2;    // 10240
constexpr int G2_SMEM = 3 * 4 * G2_BUF;  // 122880

__global__ void __launch_bounds__(256, 1) gemm2_kernel(
    const __nv_bfloat16* __restrict__ Eh, const __nv_bfloat16* __restrict__ El,
    const __nv_bfloat16* __restrict__ Wh, const __nv_bfloat16* __restrict__ Wl,
    float* __restrict__ XZ)
{
    extern __shared__ char sm[];
    const int s = blockIdx.z;
    const __nv_bfloat16* ah = Eh + (size_t)s * NM * NBP;
    const __nv_bfloat16* al = El + (size_t)s * NM * NBP;
    const __nv_bfloat16* bh = Wh + (size_t)s * G4H * KE_PAD;
    const __nv_bfloat16* bl = Wl + (size_t)s * G4H * KE_PAD;
    float* xz = XZ + (size_t)s * NM * G4H;
    const int m0 = blockIdx.x * 128;
    const int n0 = blockIdx.y * 128;

    const uint32_t sb = smem_u32(sm);
    char* AHb = sm;
    char* ALb = sm + 3 * G2_BUF;
    char* BHb = sm + 6 * G2_BUF;
    char* BLb = sm + 9 * G2_BUF;

    const int tid = threadIdx.x;
    const int lane = tid & 31, warp = tid >> 5;
    const int wm = (warp >> 2) * 64, wn = (warp & 3) * 32;
    const int qrow = lane >> 2, qcol = (lane & 3) * 2;

    auto stage = [&](int it, int buf) {
        const int k0 = it * 32;
        uint32_t dAH = sb + (uint32_t)(AHb - sm) + buf * G2_BUF;
        uint32_t dAL = sb + (uint32_t)(ALb - sm) + buf * G2_BUF;
        uint32_t dBH = sb + (uint32_t)(BHb - sm) + buf * G2_BUF;
        uint32_t dBL = sb + (uint32_t)(BLb - sm) + buf * G2_BUF;
#pragma unroll
        for (int x = tid; x < 512; x += 256) {
            int row = x >> 2, seg = x & 3;
            uint32_t so = (uint32_t)(row * KST + seg * 8) * 2;
            size_t ga = (size_t)(m0 + row) * NBP + k0 + seg * 8;
            size_t gb = (size_t)(n0 + row) * KE_PAD + k0 + seg * 8;
            cpasync16(dAH + so, ah + ga);
            cpasync16(dAL + so, al + ga);
            cpasync16(dBH + so, bh + gb);
            cpasync16(dBL + so, bl + gb);
        }
    };

    stage(0, 0); CP_COMMIT();
    stage(1, 1); CP_COMMIT();
    CP_WAIT0();
    __syncthreads();

    float c[4][4][4];
#pragma unroll
    for (int i = 0; i < 4; i++)
#pragma unroll
        for (int j = 0; j < 4; j++)
#pragma unroll
            for (int r = 0; r < 4; r++) c[i][j][r] = 0.f;

    const int iters = KE_PAD / 32;  // 10
    for (int it = 0; it < iters; ++it) {
        const int cur = it % 3;
        const bool pf = (it + 2 < iters);
        if (pf) { stage(it + 2, (it + 2) % 3); CP_COMMIT(); }
        if (pf) { CP_WAIT1(); } else { CP_WAIT0(); }
        compute_chunk<4, 4>(AHb + cur * G2_BUF, ALb + cur * G2_BUF,
                            BHb + cur * G2_BUF, BLb + cur * G2_BUF,
                            wm, wn, qrow, qcol, c);
        __syncthreads();
    }

#pragma unroll
    for (int i = 0; i < 4; i++) {
        int r0 = m0 + wm + i * 16 + qrow;
#pragma unroll
        for (int j = 0; j < 4; j++) {
            int col = n0 + wn + j * 8 + qcol;
            *(float2*)&xz[(size_t)r0 * G4H + col]       = make_float2(c[i][j][0], c[i][j][1]);
            *(float2*)&xz[(size_t)(r0 + 8) * G4H + col] = make_float2(c[i][j][2], c[i][j][3]);
        }
    }
}

// =====================================================================
// LSTM recurrence (R6 version: scalar coalesced Wr reads).
// =====================================================================
__global__ void __launch_bounds__(512) lstm_kernel(
    const float* __restrict__ Wl1, const float* __restrict__ Wl2,
    const float* __restrict__ lng1, const float* __restrict__ lnb1,
    const float* __restrict__ lng2, const float* __restrict__ lnb2)
{
    int s = blockIdx.y;
    const float* Wr  = (s ? Wl2 : Wl1) + NE * G4H;
    const float* lng = s ? lng2 : lng1;
    const float* lnb = s ? lnb2 : lnb1;
    const float* xz  = g_xz + (size_t)s * NM * G4H;

    int b0   = blockIdx.x * 4;
    int col  = threadIdx.x;
    int w    = threadIdx.x >> 5;
    int lane = threadIdx.x & 31;
    int rrl  = threadIdx.x >> 7;
    int idx  = threadIdx.x & 127;

    __shared__ float h_sh[4][128];
    __shared__ float zbuf[4][512];
    __shared__ float mu_s[4][4], rstd_s[4][4];
    __shared__ float wp1[16], wp2[16];

    h_sh[rrl][idx] = 0.f;
    float c_val = 0.f;

    float gi = lng[idx],       gj = lng[128 + idx], gf = lng[256 + idx];
    float go = lng[384 + idx], gc = lng[512 + idx];
    float bi = lnb[idx],       bj = lnb[128 + idx], bf = lnb[256 + idx];
    float bo = lnb[384 + idx], bc = lnb[512 + idx];
    __syncthreads();

    for (int t = 0; t < NT_STEPS; t++) {
        float a0 = xz[(size_t)((b0 + 0) * NT_STEPS + t) * G4H + col];
        float a1 = xz[(size_t)((b0 + 1) * NT_STEPS + t) * G4H + col];
        float a2 = xz[(size_t)((b0 + 2) * NT_STEPS + t) * G4H + col];
        float a3 = xz[(size_t)((b0 + 3) * NT_STEPS + t) * G4H + col];

#pragma unroll 8
        for (int k = 0; k < NH; k += 4) {
            float4 h0 = *(const float4*)&h_sh[0][k];
            float4 h1 = *(const float4*)&h_sh[1][k];
            float4 h2 = *(const float4*)&h_sh[2][k];
            float4 h3 = *(const float4*)&h_sh[3][k];
            float w0 = Wr[(k + 0) * G4H + col];
            float w1 = Wr[(k + 1) * G4H + col];
            float w2 = Wr[(k + 2) * G4H + col];
            float w3 = Wr[(k + 3) * G4H + col];
            a0 = fmaf(h0.x, w0, fmaf(h0.y, w1, fmaf(h0.z, w2, fmaf(h0.w, w3, a0))));
            a1 = fmaf(h1.x, w0, fmaf(h1.y, w1, fmaf(h1.z, w2, fmaf(h1.w, w3, a1))));
            a2 = fmaf(h2.x, w0, fmaf(h2.y, w1, fmaf(h2.z, w2, fmaf(h2.w, w3, a2))));
            a3 = fmaf(h3.x, w0, fmaf(h3.y, w1, fmaf(h3.z, w2, fmaf(h3.w, w3, a3))));
        }
        zbuf[0][col] = a0; zbuf[1][col] = a1; zbuf[2][col] = a2; zbuf[3][col] = a3;
        __syncthreads();

        {
            int rr = w >> 2, gg = w & 3;
            float s1 = 0.f, s2 = 0.f;
#pragma unroll
            for (int i = 0; i < 4; i++) {
                float v = zbuf[rr][gg * 128 + lane + 32 * i];
                s1 += v;
                s2 = fmaf(v, v, s2);
            }
#pragma unroll
            for (int off = 16; off; off >>= 1) {
                s1 += __shfl_xor_sync(0xffffffffu, s1, off);
                s2 += __shfl_xor_sync(0xffffffffu, s2, off);
            }
            if (lane == 0) {
                float mu  = s1 * (1.f / 128.f);
                float var = fmaxf(s2 * (1.f / 128.f) - mu * mu, 0.f);
                mu_s[rr][gg]   = mu;
                rstd_s[rr][gg] = rsqrtf(var + 1e-12f);
            }
        }
        __syncthreads();

        int r = rrl;
        float zi = (zbuf[r][idx]       - mu_s[r][0]) * rstd_s[r][0] * gi + bi;
        float zj = (zbuf[r][128 + idx] - mu_s[r][1]) * rstd_s[r][1] * gj + bj;
        float zf = (zbuf[r][256 + idx] - mu_s[r][2]) * rstd_s[r][2] * gf + bf;
        float zo = (zbuf[r][384 + idx] - mu_s[r][3]) * rstd_s[r][3] * go + bo;
        float cn = c_val * sigmoidf(zf + 1.f) + sigmoidf(zi) * fmaxf(zj, 0.f);
        c_val = cn;

        float s1 = cn, s2 = cn * cn;
#pragma unroll
        for (int off = 16; off; off >>= 1) {
            s1 += __shfl_xor_sync(0xffffffffu, s1, off);
            s2 += __shfl_xor_sync(0xffffffffu, s2, off);
        }
        if (lane == 0) { wp1[w] = s1; wp2[w] = s2; }
        __syncthreads();
        float ss1 = wp1[4 * r] + wp1[4 * r + 1] + wp1[4 * r + 2] + wp1[4 * r + 3];
        float ss2 = wp2[4 * r] + wp2[4 * r + 1] + wp2[4 * r + 2] + wp2[4 * r + 3];
        float mu_c   = ss1 * (1.f / 128.f);
        float var_c  = fmaxf(ss2 * (1.f / 128.f) - mu_c * mu_c, 0.f);
        float rstd_c = rsqrtf(var_c + 1e-12f);

        float hn = fmaxf((cn - mu_c) * rstd_c * gc + bc, 0.f) * sigmoidf(zo);
        h_sh[r][idx] = hn;
        g_o[(((size_t)s * NB + b0 + r) * NT_STEPS + t) * NH + idx] = hn;
        __syncthreads();
    }
}

// =====================================================================
// Attention + fc1.
// =====================================================================
__global__ void __launch_bounds__(512) attn_fc1_kernel(
    const float* __restrict__ v1, const float* __restrict__ Wo1, const float* __restrict__ bo1,
    const float* __restrict__ v2, const float* __restrict__ Wo2, const float* __restrict__ bo2)
{
    int s = blockIdx.y, b = blockIdx.x;
    const float* vv = s ? v2  : v1;
    const float* Wo = s ? Wo2 : Wo1;
    const float* bo = s ? bo2 : bo1;
    const float* ob = g_o + ((size_t)(s * NB + b) * NT_STEPS) * NH;

    __shared__ float sc[64];
    __shared__ float ctx[128];
    int w = threadIdx.x >> 5, lane = threadIdx.x & 31;

    for (int t = w; t < NT_STEPS; t += 16) {
        float p = 0.f;
#pragma unroll
        for (int i = 0; i < 4; i++)
            p = fmaf(ob[t * NH + lane + 32 * i], vv[lane + 32 * i], p);
#pragma unroll
        for (int off = 16; off; off >>= 1) p += __shfl_xor_sync(0xffffffffu, p, off);
        if (lane == 0) sc[t] = p;
    }
    __syncthreads();

    if (w == 0) {
        float v0 = sc[lane];
        float vb = (lane + 32 < NT_STEPS) ? sc[lane + 32] : -1e30f;
        float mx = fmaxf(v0, vb);
#pragma unroll
        for (int off = 16; off; off >>= 1) mx = fmaxf(mx, __shfl_xor_sync(0xffffffffu, mx, off));
        float e0 = expf(v0 - mx);
        float e1 = (lane + 32 < NT_STEPS) ? expf(vb - mx) : 0.f;
        float sm = e0 + e1;
#pragma unroll
        for (int off = 16; off; off >>= 1) sm += __shfl_xor_sync(0xffffffffu, sm, off);
        float inv = 1.f / sm;
        sc[lane] = e0 * inv;
        if (lane + 32 < NT_STEPS) sc[lane + 32] = e1 * inv;
    }
    __syncthreads();

    if (threadIdx.x < NH) {
        float p = 0.f;
        for (int t = 0; t < NT_STEPS; t++) p = fmaf(sc[t], ob[t * NH + threadIdx.x], p);
        ctx[threadIdx.x] = p;
    }
    __syncthreads();

    int j = threadIdx.x;
    float accv = bo[j];
#pragma unroll 4
    for (int h = 0; h < NH; h++) accv = fmaf(ctx[h], Wo[h * 512 + j], accv);
    g_a[(size_t)b * 1024 + s * 512 + j] = fmaxf(accv, 0.f);
}

// =====================================================================
// fc2 + fc3.
// =====================================================================
__global__ void __launch_bounds__(512) fc23_kernel(
    const float* __restrict__ Wh, const float* __restrict__ bh,
    const float* __restrict__ Wout, const float* __restrict__ bout,
    float* __restrict__ out)
{
    int b0 = blockIdx.x * 4;
    __shared__ float a_sh[4][1024];
    __shared__ float hid[4][512];
    int tid = threadIdx.x;

#pragma unroll
    for (int p = 0; p < 8; p++) {
        int i = p * 512 + tid;
        a_sh[i >> 10][i & 1023] = g_a[(size_t)b0 * 1024 + i];
    }
    __syncthreads();

    float acc0 = bh[tid], acc1 = bh[tid], acc2 = bh[tid], acc3 = bh[tid];
    for (int k = 0; k < 1024; k++) {
        float wv = Wh[k * 512 + tid];
        acc0 = fmaf(a_sh[0][k], wv, acc0);
        acc1 = fmaf(a_sh[1][k], wv, acc1);
        acc2 = fmaf(a_sh[2][k], wv, acc2);
        acc3 = fmaf(a_sh[3][k], wv, acc3);
    }
    hid[0][tid] = fmaxf(acc0, 0.f);
    hid[1][tid] = fmaxf(acc1, 0.f);
    hid[2][tid] = fmaxf(acc2, 0.f);
    hid[3][tid] = fmaxf(acc3, 0.f);
    __syncthreads();

    int w = tid >> 5, lane = tid & 31;
    if (w < 8) {
        int r = w >> 1, oc = w & 1;
        float p = 0.f;
#pragma unroll
        for (int i = 0; i < 16; i++) {
            int k = lane + 32 * i;
            p = fmaf(hid[r][k], Wout[k * 2 + oc], p);
        }
#pragma unroll
        for (int off = 16; off; off >>= 1) p += __shfl_xor_sync(0xffffffffu, p, off);
        if (lane == 0) out[(b0 + r) * 2 + oc] = p + bout[oc];
    }
}

// =====================================================================
extern "C" void kernel_launch(void* const* d_in, const int* in_sizes, int n_in,
                              void* d_out, int out_size)
{
    const float* x1   = (const float*)d_in[0];
    const float* x2   = (const float*)d_in[1];
    const float* em1  = (const float*)d_in[2];
    const float* em2  = (const float*)d_in[3];
    const float* Wl1  = (const float*)d_in[4];
    const float* Wl2  = (const float*)d_in[5];
    const float* lng1 = (const float*)d_in[6];
    const float* lnb1 = (const float*)d_in[7];
    const float* lng2 = (const float*)d_in[8];
    const float* lnb2 = (const float*)d_in[9];
    const float* v1   = (const float*)d_in[10];
    const float* Wo1  = (const float*)d_in[11];
    const float* bo1  = (const float*)d_in[12];
    const float* v2   = (const float*)d_in[13];
    const float* Wo2  = (const float*)d_in[14];
    const float* bo2  = (const float*)d_in[15];
    const float* Wh   = (const float*)d_in[16];
    const float* bh   = (const float*)d_in[17];
    const float* Wout = (const float*)d_in[18];
    const float* bout = (const float*)d_in[19];
    float* out = (float*)d_out;

    float *pxz;
    __nv_bfloat16 *pehi, *pelo, *peThi, *peTlo, *pwThi, *pwTlo;
    cudaGetSymbolAddress((void**)&pxz,   g_xz);
    cudaGetSymbolAddress((void**)&pehi,  g_ehi);
    cudaGetSymbolAddress((void**)&pelo,  g_elo);
    cudaGetSymbolAddress((void**)&peThi, g_eThi);
    cudaGetSymbolAddress((void**)&peTlo, g_eTlo);
    cudaGetSymbolAddress((void**)&pwThi, g_wThi);
    cudaGetSymbolAddress((void**)&pwTlo, g_wTlo);

    cudaFuncSetAttribute(gemm1_kernel, cudaFuncAttributeMaxDynamicSharedMemorySize, G1_SMEM);
    cudaFuncSetAttribute(gemm2_kernel, cudaFuncAttributeMaxDynamicSharedMemorySize, G2_SMEM);

    // 0) one-time weight reshapes
    convT_kernel<<<dim3(KV_PAD / 32, NBP / 32, 2), dim3(32, 32)>>>(
        em1, em2, NV, NE, NE, KV_PAD, NBP, peThi, peTlo, (size_t)NBP * KV_PAD);
    convT_kernel<<<dim3(KE_PAD / 32, G4H / 32, 2), dim3(32, 32)>>>(
        Wl1, Wl2, NE, G4H, G4H, KE_PAD, G4H, pwThi, pwTlo, (size_t)G4H * KE_PAD);

    // 1) embeddings: e = X @ embed  (R7 gemm1, measured 842us: 736 CTAs)
    gemm1_kernel<<<dim3(4, NM / 64, 2), 128, G1_SMEM>>>(
        x1, x2, peThi, peTlo, pehi, pelo);

    // 2) gate preactivations: xz = e @ W[:300]  (R10 gemm2, measured 52us)
    gemm2_kernel<<<dim3(NM / 128, 4, 2), 256, G2_SMEM>>>(
        pehi, pelo, pwThi, pwTlo, pxz);

    // 3) sequential LSTM recurrence (R6 version)
    lstm_kernel<<<dim3(NB / 4, 2), 512>>>(Wl1, Wl2, lng1, lnb1, lng2, lnb2);

    // 4) attention + fc1
    attn_fc1_kernel<<<dim3(NB, 2), 512>>>(v1, Wo1, bo1, v2, Wo2, bo2);

    // 5) fc2 + logits
    fc23_kernel<<<NB / 4, 512>>>(Wh, bh, Wout, bout, out);
}